// round 14
// baseline (speedup 1.0000x reference)
#include <cuda_runtime.h>
#include <cuda_fp16.h>
#include <cstdint>
#include <math.h>

// ---------------- problem constants ----------------
constexpr int NB   = 1024;
constexpr int NH   = 1024;
constexpr int NI   = 69;
constexpr int NSRC = 50;
constexpr int NDEC = 24;
constexpr int NT   = 74;
constexpr int KX   = 128;
constexpr int KA   = NH + KX;     // 1152
constexpr int NCHUNK = KA / 64;   // 18
constexpr int NSTEP = 2 * NT;     // 148

constexpr int STG  = 32768;               // A 8KB + B 3x8KB per stage
constexpr int SPILL_OFF = 3 * STG;        // 98304: h_n spill [64][68] fp32
constexpr int SMEM_BYTES = SPILL_OFF + 64 * 68 * 4;   // 115712 (2 CTAs/SM)
constexpr int W1_OFF = 2 * STG;           // fc1: h tile @ stage2, w1 @ stage2+8KB

// ---------------- device scratch ----------------
__device__ __align__(16) float  g_h32[2][NB * NH];
__device__ __align__(16) __half g_h16[2][NB * NH];   // fp16 hidden state
__device__ __align__(16) __half g_xall[NT * NB * KX];// all encode frames fp16 (padded)
__device__ __align__(16) __half g_xdec[NB * KX];     // decode-time x fp16 (padded)
__device__ __align__(16) __half g_wB[4 * KA * NH];   // [g][k][j] fp16
__device__ __align__(16) __half g_w1h[2 * NH * 64];  // fc1 w [slot][j][i-in-slot] fp16
__device__ __align__(16) float  g_x32[NB * KX];
__device__ __align__(16) float  g_outb[NT * NB * NI];
__device__ __align__(16) float  g_part[16 * NB * NI];

// cross-step sync flags (reset each replay by k_rst)
__device__ unsigned g_doneF[NSTEP][16];   // per-step per-j-tile: 16 m-CTAs each
__device__ unsigned g_allF[NSTEP];        // per-step: 256 CTAs
__device__ unsigned g_xdoneF[NT];         // per decode output: 256 slices

// ---------------- asm helpers (base PTX only) ----------------
__device__ __forceinline__ uint32_t smem_u32(const void* p) {
    uint32_t a;
    asm("{ .reg .u64 t; cvta.to.shared.u64 t, %1; cvt.u32.u64 %0, t; }" : "=r"(a) : "l"(p));
    return a;
}
__device__ __forceinline__ void cp16(uint32_t dst, const void* src) {
    asm volatile("cp.async.cg.shared.global [%0], [%1], 16;" :: "r"(dst), "l"(src));
}
__device__ __forceinline__ void cp_commit() {
    asm volatile("cp.async.commit_group;" ::: "memory");
}
__device__ __forceinline__ void ldsm4(uint32_t* r, uint32_t addr) {
    asm volatile("ldmatrix.sync.aligned.m8n8.x4.shared.b16 {%0,%1,%2,%3}, [%4];"
        : "=r"(r[0]), "=r"(r[1]), "=r"(r[2]), "=r"(r[3]) : "r"(addr));
}
__device__ __forceinline__ void ldsm4t(uint32_t* r, uint32_t addr) {
    asm volatile("ldmatrix.sync.aligned.m8n8.x4.trans.shared.b16 {%0,%1,%2,%3}, [%4];"
        : "=r"(r[0]), "=r"(r[1]), "=r"(r[2]), "=r"(r[3]) : "r"(addr));
}
__device__ __forceinline__ void mma16816(float* d, const uint32_t* a, const uint32_t* b) {
    asm volatile("mma.sync.aligned.m16n8k16.row.col.f32.f16.f16.f32 "
        "{%0,%1,%2,%3}, {%4,%5,%6,%7}, {%8,%9}, {%0,%1,%2,%3};"
        : "+f"(d[0]), "+f"(d[1]), "+f"(d[2]), "+f"(d[3])
        : "r"(a[0]), "r"(a[1]), "r"(a[2]), "r"(a[3]), "r"(b[0]), "r"(b[1]));
}
__device__ __forceinline__ uint32_t sw(uint32_t bo) { return bo ^ ((bo >> 3) & 0x70); }
__device__ __forceinline__ unsigned ldacq(const unsigned* p) {
    unsigned v;
    asm volatile("ld.acquire.gpu.u32 %0, [%1];" : "=r"(v) : "l"(p) : "memory");
    return v;
}
__device__ __forceinline__ void spinwait(const unsigned* p, unsigned tgt) {
    while (ldacq(p) < tgt) __nanosleep(64);
}

// fast sigmoid: EX2 + RCP + 1 Newton step (rel err ~1e-7)
__device__ __forceinline__ float sigf(float x) {
    float t = fminf(fmaxf(x, -30.f), 30.f);
    float e;
    asm("ex2.approx.f32 %0, %1;" : "=f"(e) : "f"(-1.4426950408889634f * t));
    float den = 1.0f + e;
    float r;
    asm("rcp.approx.f32 %0, %1;" : "=f"(r) : "f"(den));
    return r * (2.0f - den * r);
}
__device__ __forceinline__ float tanhfast(float x) { return 1.0f - 2.0f * sigf(-2.0f * x); }

// ---------------- prep kernels ----------------
__global__ void k_rst() {
    int i = blockIdx.x * blockDim.x + threadIdx.x;
    if (i < NSTEP * 16) ((unsigned*)g_doneF)[i] = 0;
    if (i < NSTEP) g_allF[i] = 0;
    if (i < NT) g_xdoneF[i] = 0;
}

__global__ void k_prep(const float* __restrict__ w_ih, const float* __restrict__ w_hh) {
    size_t idx = (size_t)blockIdx.x * blockDim.x + threadIdx.x;
    if (idx >= (size_t)4 * KA * NH) return;
    int j = (int)(idx % NH);
    int t = (int)(idx / NH);
    int k = t % KA;
    int g = t / KA;
    float v = 0.0f;
    if (g == 0) {
        if (k < NH) v = w_hh[(size_t)j * NH + k];
        else if (k - NH < NI) v = w_ih[(size_t)j * NI + (k - NH)];
    } else if (g == 1) {
        if (k < NH) v = w_hh[(size_t)(NH + j) * NH + k];
        else if (k - NH < NI) v = w_ih[(size_t)(NH + j) * NI + (k - NH)];
    } else if (g == 2) {
        if (k >= NH && k - NH < NI) v = w_ih[(size_t)(2 * NH + j) * NI + (k - NH)];
    } else {
        if (k < NH) v = w_hh[(size_t)(2 * NH + j) * NH + k];
    }
    g_wB[idx] = __float2half(v);
}

__global__ void k_prepw(const float* __restrict__ fc1w) {
    int idx = blockIdx.x * blockDim.x + threadIdx.x;
    if (idx >= 2 * NH * 64) return;
    int n = idx & 63;
    int j = (idx >> 6) & (NH - 1);
    int s = idx >> 16;
    int i = s * 64 + n;
    float v = (i < NI) ? fc1w[(size_t)i * NH + j] : 0.0f;
    g_w1h[idx] = __float2half(v);
}

__global__ void k_setxall(const float* __restrict__ enc, const float* __restrict__ dec) {
    size_t idx = (size_t)blockIdx.x * blockDim.x + threadIdx.x;
    if (idx >= (size_t)NT * NB * KX) return;
    int c = (int)(idx & (KX - 1));
    size_t r = idx >> 7;
    int b = (int)(r & (NB - 1));
    int t = (int)(r >> 10);
    float v = 0.0f;
    if (c < NI) {
        if (t < NSRC) v = enc[((size_t)b * NSRC + t) * NI + c];
        else          v = dec[((size_t)b * NDEC + (t - NSRC)) * NI + c];
    }
    g_xall[idx] = __float2half(v);
    if (t == 0) g_x32[(size_t)b * KX + c] = v;
}

__global__ void k_init() {
    int idx = blockIdx.x * blockDim.x + threadIdx.x;
    if (idx < NB * NH) {
        g_h16[0][idx] = __float2half(0.0f);
        g_h32[0][idx] = 0.0f;
    }
    if (idx < NB * KX) g_xdec[idx] = __float2half(0.0f);
}

// ---------------- persistent fused GRU: all 148 steps ----------------
// grid (16 j-tiles, 16 m-tiles) = 256 CTAs, 384 thr, 2 CTAs/SM -> all resident.
// Cross-step sync: per-column-block flags (h), full-step counters (outred).
__global__ void __launch_bounds__(384, 2)
k_gru_all(const float* __restrict__ bih, const float* __restrict__ bhh,
          const float* __restrict__ fc1b) {
    extern __shared__ char sm[];
    const uint32_t sb = smem_u32(sm);
    const int tid = threadIdx.x;
    const int wid = tid >> 5, l = tid & 31;
    const int gate = wid >> 2;
    const int mq = (wid >> 1) & 1, nh = wid & 1;
    const int m0 = blockIdx.y * 64;
    const int jt = blockIdx.x;
    const int j0 = jt * 64;
    const int cta = blockIdx.y * 16 + blockIdx.x;   // 0..255

    float* spill = (float*)(sm + SPILL_OFF);   // [64][68]
    float* sC = (float*)sm;                    // epilogue overlay [64][196]

    #pragma unroll 1
    for (int s = 0; s < NSTEP; ++s) {
        const int cur = s & 1, nxt = cur ^ 1;
        const __half* hcur = g_h16[cur];
        const __half* xb = (s < NT) ? (g_xall + (size_t)s * NB * KX)
                         : (s == NT) ? g_xall : g_xdec;
        const int c0 = (s == 0) ? 16 : 0;
        const int do_fc1 = (s >= NT);
        const int tprev = s - NT - 1;   // valid when s > NT

        float d[2][4][4] = {};

        auto load_chunk = [&](int c) {
            // dataflow gates
            if (c < 16) {
                if (s > 0) spinwait(&g_doneF[s - 1][c], 16);
            } else if (s > NT) {
                spinwait(&g_xdoneF[tprev], 256);
            }
            const uint32_t st = sb + (c % 3) * STG;
            #pragma unroll
            for (int i = 0; i < 6; i++) {
                int v = tid + i * 384;
                if (v < 512) {
                    int m = v >> 3, kg = v & 7;
                    const __half* src = (c < 16)
                        ? hcur + (size_t)(m0 + m) * NH + c * 64 + kg * 8
                        : xb   + (size_t)(m0 + m) * KX + (c - 16) * 64 + kg * 8;
                    cp16(st + m * 128 + ((kg ^ (m & 7)) << 4), src);
                } else if (v < 2048) {
                    int u = v - 512;
                    int tb = u >> 9;
                    int r = (u >> 3) & 63, cg = u & 7;
                    int g = (tb < 2) ? tb : ((c < 16) ? 3 : 2);
                    cp16(st + 8192 + tb * 8192 + r * 128 + ((cg ^ (r & 7)) << 4),
                         g_wB + ((size_t)g * KA + c * 64 + r) * NH + j0 + cg * 8);
                }
            }
            cp_commit();
        };

        load_chunk(c0);
        load_chunk(c0 + 1);
        for (int c = c0; c < NCHUNK; c++) {
            if (c < NCHUNK - 1) {
                asm volatile("cp.async.wait_group 1;" ::: "memory");
            } else {
                asm volatile("cp.async.wait_group 0;" ::: "memory");
            }
            __syncthreads();

            if (c + 2 < NCHUNK) load_chunk(c + 2);

            // folded outred for previous decode output (overlaps in-flight loads)
            if (c == 8 && s > NT) {
                spinwait(&g_allF[s - 1], 256);
                for (int e = tid; e < 276; e += 384) {
                    int idx = cta * 276 + e;
                    int b = idx / NI, i = idx - b * NI;
                    float sv = g_x32[(size_t)b * KX + i] + fc1b[i];
                    #pragma unroll
                    for (int p = 0; p < 16; p++)
                        sv += g_part[(size_t)p * NB * NI + idx];
                    g_outb[(size_t)tprev * NB * NI + idx] = sv;
                    g_x32[(size_t)b * KX + i] = sv;
                    g_xdec[(size_t)b * KX + i] = __float2half(sv);
                }
                __syncthreads();
                if (tid == 0) {
                    __threadfence();
                    atomicAdd(&g_xdoneF[tprev], 1u);
                }
            }

            // n-slot boundary: stash h_n accum, restart for i_n
            if (c == 16 && gate == 2) {
                #pragma unroll
                for (int mt = 0; mt < 2; mt++) {
                    int r0 = mq * 32 + mt * 16 + (l >> 2);
                    int cc = nh * 32 + (l & 3) * 2;
                    #pragma unroll
                    for (int nb = 0; nb < 4; nb++) {
                        *(float2*)&spill[r0 * 68 + nb * 8 + cc] =
                            make_float2(d[mt][nb][0], d[mt][nb][1]);
                        *(float2*)&spill[(r0 + 8) * 68 + nb * 8 + cc] =
                            make_float2(d[mt][nb][2], d[mt][nb][3]);
                        d[mt][nb][0] = d[mt][nb][1] = d[mt][nb][2] = d[mt][nb][3] = 0.0f;
                    }
                }
            }

            const uint32_t st = sb + (c % 3) * STG;
            const uint32_t bslot = st + 8192 + gate * 8192;
            #pragma unroll
            for (int kk = 0; kk < 4; kk++) {
                uint32_t b[2][4];
                #pragma unroll
                for (int nq = 0; nq < 2; nq++) {
                    int k = kk * 16 + (l & 15);
                    int ng = nh * 4 + nq * 2 + (l >> 4);
                    ldsm4t(b[nq], bslot + k * 128 + ((ng ^ (k & 7)) << 4));
                }
                uint32_t a[2][4];
                #pragma unroll
                for (int mt = 0; mt < 2; mt++) {
                    int m = mq * 32 + mt * 16 + (l & 15);
                    int kg = kk * 2 + (l >> 4);
                    ldsm4(a[mt], st + m * 128 + ((kg ^ (m & 7)) << 4));
                }
                #pragma unroll
                for (int mt = 0; mt < 2; mt++)
                    #pragma unroll
                    for (int nb = 0; nb < 4; nb++)
                        mma16816(d[mt][nb], a[mt], b[nb >> 1] + (nb & 1) * 2);
            }
        }
        __syncthreads();   // all compute done; stages reusable

        // fc1 weight slice load (overlaps epilogue)
        if (do_fc1) {
            #pragma unroll
            for (int i = 0; i < 3; i++) {
                int v = tid + i * 384;
                if (v < 1024) {
                    int sl = v >> 9, r = (v >> 3) & 63, cg = v & 7;
                    cp16(sb + W1_OFF + 8192 + sl * 8192 + r * 128 + ((cg ^ (r & 7)) << 4),
                         g_w1h + ((size_t)sl * NH + j0 + r) * 64 + cg * 8);
                }
            }
            cp_commit();
        }

        // epilogue: planes r | z | i_n in sC; h_n in spill
        #pragma unroll
        for (int mt = 0; mt < 2; mt++) {
            int r0 = mq * 32 + mt * 16 + (l >> 2);
            int cc = gate * 64 + nh * 32 + (l & 3) * 2;
            #pragma unroll
            for (int nb = 0; nb < 4; nb++) {
                *(float2*)&sC[r0 * 196 + cc + nb * 8] =
                    make_float2(d[mt][nb][0], d[mt][nb][1]);
                *(float2*)&sC[(r0 + 8) * 196 + cc + nb * 8] =
                    make_float2(d[mt][nb][2], d[mt][nb][3]);
            }
        }
        __syncthreads();

        #pragma unroll
        for (int i = 0; i < 11; i++) {
            int idx = i * 384 + tid;
            if (idx >= 64 * 64) break;
            int m = idx >> 6, j = idx & 63;
            int jg = j0 + j;
            float rc = sC[m * 196 + j];
            float zc = sC[m * 196 + 64 + j];
            float ic = sC[m * 196 + 128 + j];
            float hc = spill[m * 68 + j];
            float br  = __ldg(&bih[jg]) + __ldg(&bhh[jg]);
            float bz  = __ldg(&bih[NH + jg]) + __ldg(&bhh[NH + jg]);
            float bin = __ldg(&bih[2 * NH + jg]);
            float bhn = __ldg(&bhh[2 * NH + jg]);
            float r = sigf(rc + br);
            float z = sigf(zc + bz);
            float n = tanhfast(ic + bin + r * (hc + bhn));
            float hold = g_h32[cur][(size_t)(m0 + m) * NH + jg];
            float hnew = (1.0f - z) * n + z * hold;
            g_h32[nxt][(size_t)(m0 + m) * NH + jg] = hnew;
            __half h16 = __float2half(hnew);
            g_h16[nxt][(size_t)(m0 + m) * NH + jg] = h16;
            if (do_fc1)
                *(__half*)(sm + W1_OFF + sw((uint32_t)(m * 128 + j * 2))) = h16;
        }

        if (do_fc1) {
            asm volatile("cp.async.wait_group 0;" ::: "memory");
            __syncthreads();
            if (wid < 8) {
                const int wm = wid >> 2, wn = wid & 3;
                float d2[2][4][4] = {};
                const uint32_t ab = sb + W1_OFF;
                const uint32_t bb = sb + W1_OFF + 8192 + (wn >> 1) * 8192;
                #pragma unroll
                for (int kk = 0; kk < 4; kk++) {
                    uint32_t a[2][4];
                    #pragma unroll
                    for (int mt = 0; mt < 2; mt++) {
                        int m = wm * 32 + mt * 16 + (l & 15);
                        int kg = kk * 2 + (l >> 4);
                        ldsm4(a[mt], ab + m * 128 + ((kg ^ (m & 7)) << 4));
                    }
                    uint32_t b[2][4];
                    #pragma unroll
                    for (int nq = 0; nq < 2; nq++) {
                        int k = kk * 16 + (l & 15);
                        int ng = (wn & 1) * 4 + nq * 2 + (l >> 4);
                        ldsm4t(b[nq], bb + k * 128 + ((ng ^ (k & 7)) << 4));
                    }
                    #pragma unroll
                    for (int mt = 0; mt < 2; mt++)
                        #pragma unroll
                        for (int nb = 0; nb < 4; nb++)
                            mma16816(d2[mt][nb], a[mt], b[nb >> 1] + (nb & 1) * 2);
                }
                #pragma unroll
                for (int mt = 0; mt < 2; mt++) {
                    int mg = m0 + wm * 32 + mt * 16 + (l >> 2);
                    #pragma unroll
                    for (int nb = 0; nb < 4; nb++) {
                        int n = wn * 32 + nb * 8 + (l & 3) * 2;
                        size_t base = (size_t)jt * NB * NI;
                        if (n < NI)     g_part[base + (size_t)mg * NI + n]           = d2[mt][nb][0];
                        if (n + 1 < NI) g_part[base + (size_t)mg * NI + n + 1]       = d2[mt][nb][1];
                        if (n < NI)     g_part[base + (size_t)(mg + 8) * NI + n]     = d2[mt][nb][2];
                        if (n + 1 < NI) g_part[base + (size_t)(mg + 8) * NI + n + 1] = d2[mt][nb][3];
                    }
                }
            }
        }

        __syncthreads();   // all stores done before announcing
        if (tid == 0) {
            __threadfence();
            atomicAdd(&g_doneF[s][jt], 1u);
            atomicAdd(&g_allF[s], 1u);
        }
    }

    // final outred for the last decode output (t = NT-1): needed by k_final only
    spinwait(&g_allF[NSTEP - 1], 256);
    {
        const int t = NT - 1;
        for (int e = tid; e < 276; e += 384) {
            int idx = cta * 276 + e;
            int b = idx / NI, i = idx - b * NI;
            float sv = g_x32[(size_t)b * KX + i] + fc1b[i];
            #pragma unroll
            for (int p = 0; p < 16; p++)
                sv += g_part[(size_t)p * NB * NI + idx];
            g_outb[(size_t)t * NB * NI + idx] = sv;
        }
    }
}

__global__ void k_final(const float* __restrict__ fc2w, const float* __restrict__ fc2b,
                        float* __restrict__ y) {
    int b = blockIdx.x;
    float s = 0.0f;
    for (int f = threadIdx.x; f < NT * NI; f += 256) {
        int t = f / NI, i = f - t * NI;
        s += g_outb[(size_t)t * NB * NI + (size_t)b * NI + i] * fc2w[f];
    }
    __shared__ float red[256];
    red[threadIdx.x] = s;
    __syncthreads();
    for (int off = 128; off > 0; off >>= 1) {
        if (threadIdx.x < off) red[threadIdx.x] += red[threadIdx.x + off];
        __syncthreads();
    }
    if (threadIdx.x == 0)
        y[b] = 1.0f / (1.0f + expf(-(red[0] + fc2b[0])));
}

// ---------------- launch ----------------
extern "C" void kernel_launch(void* const* d_in, const int* in_sizes, int n_in,
                              void* d_out, int out_size) {
    const float* enc  = (const float*)d_in[0];
    const float* dec  = (const float*)d_in[1];
    const float* w_ih = (const float*)d_in[2];
    const float* w_hh = (const float*)d_in[3];
    const float* b_ih = (const float*)d_in[4];
    const float* b_hh = (const float*)d_in[5];
    const float* fc1w = (const float*)d_in[6];
    const float* fc1b = (const float*)d_in[7];
    const float* fc2w = (const float*)d_in[8];
    const float* fc2b = (const float*)d_in[9];
    float* y = (float*)d_out;

    cudaFuncSetAttribute(k_gru_all, cudaFuncAttributeMaxDynamicSharedMemorySize, SMEM_BYTES);

    k_rst<<<(NSTEP * 16 + 255) / 256, 256>>>();
    k_prep<<<(int)(((size_t)4 * KA * NH + 255) / 256), 256>>>(w_ih, w_hh);
    k_prepw<<<(2 * NH * 64 + 255) / 256, 256>>>(fc1w);
    k_setxall<<<(int)(((size_t)NT * NB * KX + 255) / 256), 256>>>(enc, dec);
    k_init<<<(NB * NH + 255) / 256, 256>>>();

    k_gru_all<<<dim3(16, 16), 384, SMEM_BYTES>>>(b_ih, b_hh, fc1b);

    k_final<<<NB, 256>>>(fc2w, fc2b, y);
}

// round 15
// speedup vs baseline: 1.2332x; 1.2332x over previous
#include <cuda_runtime.h>
#include <cuda_fp16.h>
#include <cstdint>
#include <math.h>

// ---------------- problem constants ----------------
constexpr int NB   = 1024;
constexpr int NH   = 1024;
constexpr int NI   = 69;
constexpr int NIP  = 72;          // padded NI (float4-friendly)
constexpr int NSRC = 50;
constexpr int NDEC = 24;
constexpr int NT   = 74;
constexpr int KX   = 128;
constexpr int KA   = NH + KX;     // 1152
constexpr int NCHUNK = KA / 64;   // 18
constexpr int NSTEP = 2 * NT;     // 148

constexpr int STG  = 32768;               // A 8KB + B 3x8KB per stage
constexpr int SPILL_OFF = 3 * STG;        // 98304: h_n spill [64][68] fp32
constexpr int SMEM_BYTES = SPILL_OFF + 64 * 68 * 4;   // 115712 (2 CTAs/SM)
constexpr int W1_OFF = 2 * STG;           // fc1: h tile @ stage2, w1 @ stage2+8KB

// ---------------- device scratch ----------------
__device__ __align__(16) float  g_h32[2][NB * NH];
__device__ __align__(16) __half g_h16[2][NB * NH];    // fp16 hidden state
__device__ __align__(16) __half g_xall[NT * NB * KX]; // all encode frames fp16 (padded)
__device__ __align__(16) __half g_xdec[NB * KX];      // decode-time x fp16 (padded)
__device__ __align__(16) __half g_wB[4 * KA * NH];    // [g][k][j] fp16
__device__ __align__(16) __half g_w1h[2 * NH * 64];   // fc1 w [slot][j][i-in-slot] fp16
__device__ __align__(16) float  g_x32p[2][NB * KX];   // fp32 x ping-pong (t parity)
__device__ __align__(16) float  g_fc1bp[NIP];         // padded fc1 bias
__device__ __align__(16) float  g_outb[NT * NB * NIP];
__device__ __align__(16) float  g_part[2][16 * NB * NIP];  // step-parity ping-pong

// ---------------- asm helpers (base PTX only) ----------------
__device__ __forceinline__ uint32_t smem_u32(const void* p) {
    uint32_t a;
    asm("{ .reg .u64 t; cvta.to.shared.u64 t, %1; cvt.u32.u64 %0, t; }" : "=r"(a) : "l"(p));
    return a;
}
__device__ __forceinline__ void cp16(uint32_t dst, const void* src) {
    asm volatile("cp.async.cg.shared.global [%0], [%1], 16;" :: "r"(dst), "l"(src));
}
__device__ __forceinline__ void cp_commit() {
    asm volatile("cp.async.commit_group;" ::: "memory");
}
__device__ __forceinline__ void ldsm4(uint32_t* r, uint32_t addr) {
    asm volatile("ldmatrix.sync.aligned.m8n8.x4.shared.b16 {%0,%1,%2,%3}, [%4];"
        : "=r"(r[0]), "=r"(r[1]), "=r"(r[2]), "=r"(r[3]) : "r"(addr));
}
__device__ __forceinline__ void ldsm4t(uint32_t* r, uint32_t addr) {
    asm volatile("ldmatrix.sync.aligned.m8n8.x4.trans.shared.b16 {%0,%1,%2,%3}, [%4];"
        : "=r"(r[0]), "=r"(r[1]), "=r"(r[2]), "=r"(r[3]) : "r"(addr));
}
__device__ __forceinline__ void mma16816(float* d, const uint32_t* a, const uint32_t* b) {
    asm volatile("mma.sync.aligned.m16n8k16.row.col.f32.f16.f16.f32 "
        "{%0,%1,%2,%3}, {%4,%5,%6,%7}, {%8,%9}, {%0,%1,%2,%3};"
        : "+f"(d[0]), "+f"(d[1]), "+f"(d[2]), "+f"(d[3])
        : "r"(a[0]), "r"(a[1]), "r"(a[2]), "r"(a[3]), "r"(b[0]), "r"(b[1]));
}
__device__ __forceinline__ uint32_t sw(uint32_t bo) { return bo ^ ((bo >> 3) & 0x70); }

// fast sigmoid: EX2 + RCP + 1 Newton step (rel err ~1e-7)
__device__ __forceinline__ float sigf(float x) {
    float t = fminf(fmaxf(x, -30.f), 30.f);
    float e;
    asm("ex2.approx.f32 %0, %1;" : "=f"(e) : "f"(-1.4426950408889634f * t));
    float den = 1.0f + e;
    float r;
    asm("rcp.approx.f32 %0, %1;" : "=f"(r) : "f"(den));
    return r * (2.0f - den * r);
}
__device__ __forceinline__ float tanhfast(float x) { return 1.0f - 2.0f * sigf(-2.0f * x); }

// ---------------- prep: per-gate K-major fp16 weights ----------------
__global__ void k_prep(const float* __restrict__ w_ih, const float* __restrict__ w_hh) {
    size_t idx = (size_t)blockIdx.x * blockDim.x + threadIdx.x;
    if (idx >= (size_t)4 * KA * NH) return;
    int j = (int)(idx % NH);
    int t = (int)(idx / NH);
    int k = t % KA;
    int g = t / KA;
    float v = 0.0f;
    if (g == 0) {
        if (k < NH) v = w_hh[(size_t)j * NH + k];
        else if (k - NH < NI) v = w_ih[(size_t)j * NI + (k - NH)];
    } else if (g == 1) {
        if (k < NH) v = w_hh[(size_t)(NH + j) * NH + k];
        else if (k - NH < NI) v = w_ih[(size_t)(NH + j) * NI + (k - NH)];
    } else if (g == 2) {
        if (k >= NH && k - NH < NI) v = w_ih[(size_t)(2 * NH + j) * NI + (k - NH)];
    } else {
        if (k < NH) v = w_hh[(size_t)(2 * NH + j) * NH + k];
    }
    g_wB[idx] = __float2half(v);
}

// fc1 weights (padded i-slots) + padded fc1 bias
__global__ void k_prepw(const float* __restrict__ fc1w, const float* __restrict__ fc1b) {
    int idx = blockIdx.x * blockDim.x + threadIdx.x;
    if (idx < NIP) g_fc1bp[idx] = (idx < NI) ? fc1b[idx] : 0.0f;
    if (idx >= 2 * NH * 64) return;
    int n = idx & 63;
    int j = (idx >> 6) & (NH - 1);
    int s = idx >> 16;
    int i = s * 64 + n;
    float v = (i < NI) ? fc1w[(size_t)i * NH + j] : 0.0f;
    g_w1h[idx] = __float2half(v);
}

// one-shot: convert ALL encode frames to fp16 padded; frame 0 also -> g_x32p[0]
__global__ void k_setxall(const float* __restrict__ enc, const float* __restrict__ dec) {
    size_t idx = (size_t)blockIdx.x * blockDim.x + threadIdx.x;
    if (idx >= (size_t)NT * NB * KX) return;
    int c = (int)(idx & (KX - 1));
    size_t r = idx >> 7;
    int b = (int)(r & (NB - 1));
    int t = (int)(r >> 10);
    float v = 0.0f;
    if (c < NI) {
        if (t < NSRC) v = enc[((size_t)b * NSRC + t) * NI + c];
        else          v = dec[((size_t)b * NDEC + (t - NSRC)) * NI + c];
    }
    g_xall[idx] = __float2half(v);
    if (t == 0) g_x32p[0][(size_t)b * KX + c] = v;
}

__global__ void k_init() {
    int idx = blockIdx.x * blockDim.x + threadIdx.x;
    if (idx < NB * NH) {
        g_h16[0][idx] = __float2half(0.0f);
        g_h32[0][idx] = 0.0f;
    }
    if (idx < NB * KX) g_xdec[idx] = __float2half(0.0f);
}

// ---------------- fused GRU step ----------------
// grid (16 j-tiles, 16 m-tiles), 384 threads = 12 warps, 2 CTAs/SM.
// warp: gate = wid>>2 (0=r,1=z,2=n-slot); mq = (wid>>1)&1; nh = wid&1.
// CTA tile 64m x 64j, warp tile 32m x 32n. 3-stage ring, one barrier/chunk.
// s>NT: folded outred for t=s-NT-1 at c==8 (own rows, reads prev-launch g_part).
// s>=NT: epilogue fc1 MMA -> g_part[s&1][jt].
__global__ void __launch_bounds__(384, 2)
k_gru(int s, const float* __restrict__ bih, const float* __restrict__ bhh) {
    extern __shared__ char sm[];
    const uint32_t sb = smem_u32(sm);
    const int tid = threadIdx.x;
    const int wid = tid >> 5, l = tid & 31;
    const int gate = wid >> 2;
    const int mq = (wid >> 1) & 1, nh = wid & 1;
    const int m0 = blockIdx.y * 64;
    const int jt = blockIdx.x;
    const int j0 = jt * 64;

    const int cur = s & 1, nxt = cur ^ 1;
    const int do_fc1 = (s >= NT);
    const int c0 = (s == 0) ? 16 : 0;
    const __half* hcur = g_h16[cur];
    const __half* xb = (s < NT) ? (g_xall + (size_t)s * NB * KX)
                     : (s == NT) ? g_xall : g_xdec;

    float d[2][4][4] = {};   // [mt][nb][frag]

    auto load_chunk = [&](int c) {
        const uint32_t st = sb + (c % 3) * STG;
        #pragma unroll
        for (int i = 0; i < 6; i++) {
            int v = tid + i * 384;
            if (v < 512) {
                int m = v >> 3, kg = v & 7;
                const __half* src = (c < 16)
                    ? hcur + (size_t)(m0 + m) * NH + c * 64 + kg * 8
                    : xb   + (size_t)(m0 + m) * KX + (c - 16) * 64 + kg * 8;
                cp16(st + m * 128 + ((kg ^ (m & 7)) << 4), src);
            } else if (v < 2048) {
                int u = v - 512;
                int tb = u >> 9;
                int r = (u >> 3) & 63, cg = u & 7;
                int g = (tb < 2) ? tb : ((c < 16) ? 3 : 2);
                cp16(st + 8192 + tb * 8192 + r * 128 + ((cg ^ (r & 7)) << 4),
                     g_wB + ((size_t)g * KA + c * 64 + r) * NH + j0 + cg * 8);
            }
        }
        cp_commit();
    };

    float* spill = (float*)(sm + SPILL_OFF);   // [64][68]

    load_chunk(c0);
    load_chunk(c0 + 1);
    for (int c = c0; c < NCHUNK; c++) {
        if (c < NCHUNK - 1) {
            asm volatile("cp.async.wait_group 1;" ::: "memory");
        } else {
            asm volatile("cp.async.wait_group 0;" ::: "memory");
        }
        __syncthreads();   // the ONLY barrier per chunk

        if (c + 2 < NCHUNK) load_chunk(c + 2);

        // folded outred (own rows; prev-launch partials; pads stay zero)
        if (c == 8 && s > NT) {
            const int t = s - NT - 1;
            const float* pp  = g_part[(s - 1) & 1];
            const float* xin = g_x32p[t & 1];
            float* xout = g_x32p[(t + 1) & 1];
            #pragma unroll 1
            for (int g = 0; g < 3; g++) {
                int grp = tid + g * 384;          // 0..1151
                int m = grp / 18, v = grp - m * 18;
                int b = m0 + m, i0 = v * 4;
                float4 acc = *(const float4*)&xin[(size_t)b * KX + i0];
                float4 bb4 = *(const float4*)&g_fc1bp[i0];
                acc.x += bb4.x; acc.y += bb4.y; acc.z += bb4.z; acc.w += bb4.w;
                #pragma unroll
                for (int p = 0; p < 16; p++) {
                    float4 pv = *(const float4*)&pp[((size_t)p * NB + b) * NIP + i0];
                    acc.x += pv.x; acc.y += pv.y; acc.z += pv.z; acc.w += pv.w;
                }
                *(float4*)&g_outb[((size_t)t * NB + b) * NIP + i0] = acc;
                *(float4*)&xout[(size_t)b * KX + i0] = acc;
                __half2* xd = (__half2*)&g_xdec[(size_t)b * KX + i0];
                xd[0] = __floats2half2_rn(acc.x, acc.y);
                xd[1] = __floats2half2_rn(acc.z, acc.w);
            }
        }

        // n-slot boundary: stash h_n accum, restart for i_n
        if (c == 16 && gate == 2) {
            #pragma unroll
            for (int mt = 0; mt < 2; mt++) {
                int r0 = mq * 32 + mt * 16 + (l >> 2);
                int cc = nh * 32 + (l & 3) * 2;
                #pragma unroll
                for (int nb = 0; nb < 4; nb++) {
                    *(float2*)&spill[r0 * 68 + nb * 8 + cc] =
                        make_float2(d[mt][nb][0], d[mt][nb][1]);
                    *(float2*)&spill[(r0 + 8) * 68 + nb * 8 + cc] =
                        make_float2(d[mt][nb][2], d[mt][nb][3]);
                    d[mt][nb][0] = d[mt][nb][1] = d[mt][nb][2] = d[mt][nb][3] = 0.0f;
                }
            }
        }

        const uint32_t st = sb + (c % 3) * STG;
        const uint32_t bslot = st + 8192 + gate * 8192;
        #pragma unroll
        for (int kk = 0; kk < 4; kk++) {
            uint32_t b[2][4];
            #pragma unroll
            for (int nq = 0; nq < 2; nq++) {
                int k = kk * 16 + (l & 15);
                int ng = nh * 4 + nq * 2 + (l >> 4);
                ldsm4t(b[nq], bslot + k * 128 + ((ng ^ (k & 7)) << 4));
            }
            uint32_t a[2][4];
            #pragma unroll
            for (int mt = 0; mt < 2; mt++) {
                int m = mq * 32 + mt * 16 + (l & 15);
                int kg = kk * 2 + (l >> 4);
                ldsm4(a[mt], st + m * 128 + ((kg ^ (m & 7)) << 4));
            }
            #pragma unroll
            for (int mt = 0; mt < 2; mt++)
                #pragma unroll
                for (int nb = 0; nb < 4; nb++)
                    mma16816(d[mt][nb], a[mt], b[nb >> 1] + (nb & 1) * 2);
        }
    }
    __syncthreads();   // all compute done; stages reusable

    // fc1 weight slice load (overlaps epilogue)
    if (do_fc1) {
        #pragma unroll
        for (int i = 0; i < 3; i++) {
            int v = tid + i * 384;
            if (v < 1024) {
                int sl = v >> 9, r = (v >> 3) & 63, cg = v & 7;
                cp16(sb + W1_OFF + 8192 + sl * 8192 + r * 128 + ((cg ^ (r & 7)) << 4),
                     g_w1h + ((size_t)sl * NH + j0 + r) * 64 + cg * 8);
            }
        }
        cp_commit();
    }

    // ---- epilogue: planes r | z | i_n in sC [64][196]; h_n in spill ----
    float* sC = (float*)sm;
    #pragma unroll
    for (int mt = 0; mt < 2; mt++) {
        int r0 = mq * 32 + mt * 16 + (l >> 2);
        int cc = gate * 64 + nh * 32 + (l & 3) * 2;
        #pragma unroll
        for (int nb = 0; nb < 4; nb++) {
            *(float2*)&sC[r0 * 196 + cc + nb * 8] =
                make_float2(d[mt][nb][0], d[mt][nb][1]);
            *(float2*)&sC[(r0 + 8) * 196 + cc + nb * 8] =
                make_float2(d[mt][nb][2], d[mt][nb][3]);
        }
    }
    __syncthreads();

    #pragma unroll
    for (int i = 0; i < 11; i++) {
        int idx = i * 384 + tid;
        if (idx >= 64 * 64) break;
        int m = idx >> 6, j = idx & 63;
        int jg = j0 + j;
        float rc = sC[m * 196 + j];
        float zc = sC[m * 196 + 64 + j];
        float ic = sC[m * 196 + 128 + j];
        float hc = spill[m * 68 + j];
        float br  = __ldg(&bih[jg]) + __ldg(&bhh[jg]);
        float bz  = __ldg(&bih[NH + jg]) + __ldg(&bhh[NH + jg]);
        float bin = __ldg(&bih[2 * NH + jg]);
        float bhn = __ldg(&bhh[2 * NH + jg]);
        float r = sigf(rc + br);
        float z = sigf(zc + bz);
        float n = tanhfast(ic + bin + r * (hc + bhn));
        float hold = g_h32[cur][(size_t)(m0 + m) * NH + jg];
        float hnew = (1.0f - z) * n + z * hold;
        g_h32[nxt][(size_t)(m0 + m) * NH + jg] = hnew;
        __half h16 = __float2half(hnew);
        g_h16[nxt][(size_t)(m0 + m) * NH + jg] = h16;
        if (do_fc1)
            *(__half*)(sm + W1_OFF + sw((uint32_t)(m * 128 + j * 2))) = h16;
    }

    if (do_fc1) {
        asm volatile("cp.async.wait_group 0;" ::: "memory");
        __syncthreads();
        // 64m x 128n(i pad) x 64k(j): 8 warps, warp tile 32x32
        if (wid < 8) {
            const int wm = wid >> 2, wn = wid & 3;
            float d2[2][4][4] = {};
            const uint32_t ab = sb + W1_OFF;
            const uint32_t bb = sb + W1_OFF + 8192 + (wn >> 1) * 8192;
            #pragma unroll
            for (int kk = 0; kk < 4; kk++) {
                uint32_t a[2][4];
                #pragma unroll
                for (int mt = 0; mt < 2; mt++) {
                    int m = wm * 32 + mt * 16 + (l & 15);
                    int kg = kk * 2 + (l >> 4);
                    ldsm4(a[mt], ab + m * 128 + ((kg ^ (m & 7)) << 4));
                }
                uint32_t b[2][4];
                #pragma unroll
                for (int nq = 0; nq < 2; nq++) {
                    int k = kk * 16 + (l & 15);
                    int ng = (wn & 1) * 4 + nq * 2 + (l >> 4);
                    ldsm4t(b[nq], bb + k * 128 + ((ng ^ (k & 7)) << 4));
                }
                #pragma unroll
                for (int mt = 0; mt < 2; mt++)
                    #pragma unroll
                    for (int nb = 0; nb < 4; nb++)
                        mma16816(d2[mt][nb], a[mt], b[nb >> 1] + (nb & 1) * 2);
            }
            // store partials padded to NIP=72 (pads explicitly zeroed)
            float* pb = g_part[s & 1] + (size_t)jt * NB * NIP;
            #pragma unroll
            for (int mt = 0; mt < 2; mt++) {
                int mg = m0 + wm * 32 + mt * 16 + (l >> 2);
                #pragma unroll
                for (int nb = 0; nb < 4; nb++) {
                    int n = wn * 32 + nb * 8 + (l & 3) * 2;
                    if (n < NIP) {
                        float2 v0, v1;
                        if (n < 68) {
                            v0 = make_float2(d2[mt][nb][0], d2[mt][nb][1]);
                            v1 = make_float2(d2[mt][nb][2], d2[mt][nb][3]);
                        } else if (n == 68) {
                            v0 = make_float2(d2[mt][nb][0], 0.0f);
                            v1 = make_float2(d2[mt][nb][2], 0.0f);
                        } else {   // n == 70
                            v0 = make_float2(0.0f, 0.0f);
                            v1 = make_float2(0.0f, 0.0f);
                        }
                        *(float2*)&pb[(size_t)mg * NIP + n]       = v0;
                        *(float2*)&pb[(size_t)(mg + 8) * NIP + n] = v1;
                    }
                }
            }
        }
    }
}

// final logit; also computes out(73) locally from step-147 partials
__global__ void k_final(const float* __restrict__ fc2w, const float* __restrict__ fc2b,
                        float* __restrict__ y) {
    int b = blockIdx.x;
    float s = 0.0f;
    // t = 0..72 from g_outb
    for (int f = threadIdx.x; f < (NT - 1) * NI; f += 256) {
        int t = f / NI, i = f - t * NI;
        s += g_outb[((size_t)t * NB + b) * NIP + i] * fc2w[f];
    }
    // t = 73 computed here (partials buffer parity: step 147 -> 1)
    if (threadIdx.x < NI) {
        int i = threadIdx.x;
        float o = g_x32p[1][(size_t)b * KX + i] + g_fc1bp[i];
        #pragma unroll
        for (int p = 0; p < 16; p++)
            o += g_part[1][((size_t)p * NB + b) * NIP + i];
        s += o * fc2w[(NT - 1) * NI + i];
    }
    __shared__ float red[256];
    red[threadIdx.x] = s;
    __syncthreads();
    for (int off = 128; off > 0; off >>= 1) {
        if (threadIdx.x < off) red[threadIdx.x] += red[threadIdx.x + off];
        __syncthreads();
    }
    if (threadIdx.x == 0)
        y[b] = 1.0f / (1.0f + expf(-(red[0] + fc2b[0])));
}

// ---------------- launch ----------------
extern "C" void kernel_launch(void* const* d_in, const int* in_sizes, int n_in,
                              void* d_out, int out_size) {
    const float* enc  = (const float*)d_in[0];
    const float* dec  = (const float*)d_in[1];
    const float* w_ih = (const float*)d_in[2];
    const float* w_hh = (const float*)d_in[3];
    const float* b_ih = (const float*)d_in[4];
    const float* b_hh = (const float*)d_in[5];
    const float* fc1w = (const float*)d_in[6];
    const float* fc1b = (const float*)d_in[7];
    const float* fc2w = (const float*)d_in[8];
    const float* fc2b = (const float*)d_in[9];
    float* y = (float*)d_out;

    cudaFuncSetAttribute(k_gru, cudaFuncAttributeMaxDynamicSharedMemorySize, SMEM_BYTES);

    k_prep<<<(int)(((size_t)4 * KA * NH + 255) / 256), 256>>>(w_ih, w_hh);
    k_prepw<<<(2 * NH * 64 + 255) / 256, 256>>>(fc1w, fc1b);
    k_setxall<<<(int)(((size_t)NT * NB * KX + 255) / 256), 256>>>(enc, dec);
    k_init<<<(NB * NH + 255) / 256, 256>>>();

    for (int s = 0; s < NSTEP; ++s)
        k_gru<<<dim3(16, 16), 384, SMEM_BYTES>>>(s, b_ih, b_hh);

    k_final<<<NB, 256>>>(fc2w, fc2b, y);
}

// round 16
// speedup vs baseline: 1.2668x; 1.0273x over previous
#include <cuda_runtime.h>
#include <cuda_fp16.h>
#include <cstdint>
#include <math.h>

// ---------------- problem constants ----------------
constexpr int NB   = 1024;
constexpr int NH   = 1024;
constexpr int NI   = 69;
constexpr int NSRC = 50;
constexpr int NDEC = 24;
constexpr int NT   = 74;
constexpr int KX   = 128;
constexpr int KA   = NH + KX;     // 1152
constexpr int NCHUNK = KA / 64;   // 18 (chunk 17 is short: only k16-group 0 non-zero)
constexpr int NSTEP = 2 * NT;     // 148

constexpr int STG  = 32768;               // A 8KB + B 3x8KB per stage
constexpr int SPILL_OFF = 3 * STG;        // 98304: h_n spill [64][68] fp32
constexpr int SMEM_BYTES = SPILL_OFF + 64 * 68 * 4;   // 115712 (2 CTAs/SM)
constexpr int W1_OFF = 2 * STG;           // fc1: h tile @ stage2, w1 @ stage2+8KB

// ---------------- device scratch ----------------
__device__ __align__(16) __half g_h16[2][NB * NH];   // fp16 hidden state (sole copy)
__device__ __align__(16) __half g_xall[NT * NB * KX];// all encode frames fp16 (padded)
__device__ __align__(16) __half g_xdec[NB * KX];     // decode-time x fp16 (padded)
__device__ __align__(16) __half g_wB[4 * KA * NH];   // [g][k][j] fp16
__device__ __align__(16) __half g_w1h[2 * NH * 64];  // fc1 w [slot][j][i-in-slot] fp16
__device__ __align__(16) float  g_x32[NB * KX];
__device__ __align__(16) float  g_outb[NT * NB * NI];
__device__ __align__(16) float  g_part[16 * NB * NI];

// ---------------- asm helpers (base PTX only) ----------------
__device__ __forceinline__ uint32_t smem_u32(const void* p) {
    uint32_t a;
    asm("{ .reg .u64 t; cvta.to.shared.u64 t, %1; cvt.u32.u64 %0, t; }" : "=r"(a) : "l"(p));
    return a;
}
__device__ __forceinline__ void cp16(uint32_t dst, const void* src) {
    asm volatile("cp.async.cg.shared.global [%0], [%1], 16;" :: "r"(dst), "l"(src));
}
__device__ __forceinline__ void cp_commit() {
    asm volatile("cp.async.commit_group;" ::: "memory");
}
__device__ __forceinline__ void ldsm4(uint32_t* r, uint32_t addr) {
    asm volatile("ldmatrix.sync.aligned.m8n8.x4.shared.b16 {%0,%1,%2,%3}, [%4];"
        : "=r"(r[0]), "=r"(r[1]), "=r"(r[2]), "=r"(r[3]) : "r"(addr));
}
__device__ __forceinline__ void ldsm4t(uint32_t* r, uint32_t addr) {
    asm volatile("ldmatrix.sync.aligned.m8n8.x4.trans.shared.b16 {%0,%1,%2,%3}, [%4];"
        : "=r"(r[0]), "=r"(r[1]), "=r"(r[2]), "=r"(r[3]) : "r"(addr));
}
__device__ __forceinline__ void mma16816(float* d, const uint32_t* a, const uint32_t* b) {
    asm volatile("mma.sync.aligned.m16n8k16.row.col.f32.f16.f16.f32 "
        "{%0,%1,%2,%3}, {%4,%5,%6,%7}, {%8,%9}, {%0,%1,%2,%3};"
        : "+f"(d[0]), "+f"(d[1]), "+f"(d[2]), "+f"(d[3])
        : "r"(a[0]), "r"(a[1]), "r"(a[2]), "r"(a[3]), "r"(b[0]), "r"(b[1]));
}
__device__ __forceinline__ uint32_t sw(uint32_t bo) { return bo ^ ((bo >> 3) & 0x70); }

// fast sigmoid: EX2 + RCP + 1 Newton step (rel err ~1e-7)
__device__ __forceinline__ float sigf(float x) {
    float t = fminf(fmaxf(x, -30.f), 30.f);
    float e;
    asm("ex2.approx.f32 %0, %1;" : "=f"(e) : "f"(-1.4426950408889634f * t));
    float den = 1.0f + e;
    float r;
    asm("rcp.approx.f32 %0, %1;" : "=f"(r) : "f"(den));
    return r * (2.0f - den * r);
}
__device__ __forceinline__ float tanhfast(float x) { return 1.0f - 2.0f * sigf(-2.0f * x); }

// ---------------- prep: per-gate K-major fp16 weights ----------------
__global__ void k_prep(const float* __restrict__ w_ih, const float* __restrict__ w_hh) {
    size_t idx = (size_t)blockIdx.x * blockDim.x + threadIdx.x;
    if (idx >= (size_t)4 * KA * NH) return;
    int j = (int)(idx % NH);
    int t = (int)(idx / NH);
    int k = t % KA;
    int g = t / KA;
    float v = 0.0f;
    if (g == 0) {
        if (k < NH) v = w_hh[(size_t)j * NH + k];
        else if (k - NH < NI) v = w_ih[(size_t)j * NI + (k - NH)];
    } else if (g == 1) {
        if (k < NH) v = w_hh[(size_t)(NH + j) * NH + k];
        else if (k - NH < NI) v = w_ih[(size_t)(NH + j) * NI + (k - NH)];
    } else if (g == 2) {
        if (k >= NH && k - NH < NI) v = w_ih[(size_t)(2 * NH + j) * NI + (k - NH)];
    } else {
        if (k < NH) v = w_hh[(size_t)(2 * NH + j) * NH + k];
    }
    g_wB[idx] = __float2half(v);
}

// fc1 weights, per 64-wide i-slot: g_w1h[s][j][n], i = s*64+n
__global__ void k_prepw(const float* __restrict__ fc1w) {
    int idx = blockIdx.x * blockDim.x + threadIdx.x;
    if (idx >= 2 * NH * 64) return;
    int n = idx & 63;
    int j = (idx >> 6) & (NH - 1);
    int s = idx >> 16;
    int i = s * 64 + n;
    float v = (i < NI) ? fc1w[(size_t)i * NH + j] : 0.0f;
    g_w1h[idx] = __float2half(v);
}

// one-shot: convert ALL encode frames to fp16 padded; frame 0 also -> g_x32
__global__ void k_setxall(const float* __restrict__ enc, const float* __restrict__ dec) {
    size_t idx = (size_t)blockIdx.x * blockDim.x + threadIdx.x;
    if (idx >= (size_t)NT * NB * KX) return;
    int c = (int)(idx & (KX - 1));
    size_t r = idx >> 7;
    int b = (int)(r & (NB - 1));
    int t = (int)(r >> 10);
    float v = 0.0f;
    if (c < NI) {
        if (t < NSRC) v = enc[((size_t)b * NSRC + t) * NI + c];
        else          v = dec[((size_t)b * NDEC + (t - NSRC)) * NI + c];
    }
    g_xall[idx] = __float2half(v);
    if (t == 0) g_x32[(size_t)b * KX + c] = v;
}

__global__ void k_init() {
    int idx = blockIdx.x * blockDim.x + threadIdx.x;
    if (idx < NB * NH) g_h16[0][idx] = __float2half(0.0f);
    if (idx < NB * KX) g_xdec[idx] = __float2half(0.0f);
}

// ---------------- fused GRU step ----------------
// grid (16 j-tiles, 16 m-tiles), 384 threads = 12 warps, 2 CTAs/SM.
// warp: gate = wid>>2 (0=r,1=z,2=n-slot); mq = (wid>>1)&1; nh = wid&1.
// CTA tile 64m x 64j, warp tile 32m x 32n. 3-stage ring, one barrier/chunk.
// chunk 17 is SHORT: only k16-group 0 carries data (x cols 64..68; rest zero).
// xsel >= 0: x = g_xall frame xsel; xsel < 0: x = g_xdec.
// c0: first chunk (16 at step 0 -- h is all-zero, skip h chunks).
// do_fc1: epilogue runs 64x128x64 fp16 MMA (h_new @ w1^T) -> g_part[jt].
__global__ void __launch_bounds__(384, 2)
k_gru(int cur, const float* __restrict__ bih, const float* __restrict__ bhh,
      int do_fc1, int xsel, int c0) {
    extern __shared__ char sm[];
    const uint32_t sb = smem_u32(sm);
    const int tid = threadIdx.x;
    const int wid = tid >> 5, l = tid & 31;
    const int gate = wid >> 2;
    const int mq = (wid >> 1) & 1, nh = wid & 1;
    const int m0 = blockIdx.y * 64;
    const int j0 = blockIdx.x * 64;
    const int jt = blockIdx.x;
    const int nxt = cur ^ 1;

    const __half* hcur = g_h16[cur];
    const __half* xb = (xsel >= 0) ? (g_xall + (size_t)xsel * NB * KX) : g_xdec;

    float d[2][4][4] = {};   // [mt][nb][frag]

    auto load_chunk = [&](int c) {
        const uint32_t st = sb + (c % 3) * STG;
        if (c == 17) {
            // short chunk: A 128 granules (64m x 2kg), B 384 (3 slots x 16k x 8cg)
            #pragma unroll
            for (int i = 0; i < 2; i++) {
                int v = tid + i * 384;
                if (v < 128) {
                    int m = v >> 1, kg = v & 1;
                    cp16(st + m * 128 + ((kg ^ (m & 7)) << 4),
                         xb + (size_t)(m0 + m) * KX + 64 + kg * 8);
                } else if (v < 512) {
                    int u = v - 128;
                    int tb = u >> 7;                 // 0..2 gate slot
                    int r = (u >> 3) & 15, cg = u & 7;
                    int g = (tb < 2) ? tb : 2;
                    cp16(st + 8192 + tb * 8192 + r * 128 + ((cg ^ (r & 7)) << 4),
                         g_wB + ((size_t)g * KA + 17 * 64 + r) * NH + j0 + cg * 8);
                }
            }
        } else {
            // full chunk: 2048 granules: A 512 (64m x 8kg), B 1536 (3 x 64k x 8cg)
            #pragma unroll
            for (int i = 0; i < 6; i++) {
                int v = tid + i * 384;
                if (v < 512) {
                    int m = v >> 3, kg = v & 7;
                    const __half* src = (c < 16)
                        ? hcur + (size_t)(m0 + m) * NH + c * 64 + kg * 8
                        : xb   + (size_t)(m0 + m) * KX + kg * 8;
                    cp16(st + m * 128 + ((kg ^ (m & 7)) << 4), src);
                } else if (v < 2048) {
                    int u = v - 512;
                    int tb = u >> 9;                 // 0..2 gate slot
                    int r = (u >> 3) & 63, cg = u & 7;
                    int g = (tb < 2) ? tb : ((c < 16) ? 3 : 2);
                    cp16(st + 8192 + tb * 8192 + r * 128 + ((cg ^ (r & 7)) << 4),
                         g_wB + ((size_t)g * KA + c * 64 + r) * NH + j0 + cg * 8);
                }
            }
        }
        cp_commit();
    };

    float* spill = (float*)(sm + SPILL_OFF);   // [64][68]

    load_chunk(c0);
    load_chunk(c0 + 1);
    for (int c = c0; c < NCHUNK; c++) {
        if (c < NCHUNK - 1) {
            asm volatile("cp.async.wait_group 1;" ::: "memory");
        } else {
            asm volatile("cp.async.wait_group 0;" ::: "memory");
        }
        __syncthreads();   // the ONLY barrier per chunk

        if (c + 2 < NCHUNK) load_chunk(c + 2);

        // n-slot boundary: stash h_n accum, restart for i_n
        // (at c0==16 this stores zeros == correct h_n for h==0)
        if (c == 16 && gate == 2) {
            #pragma unroll
            for (int mt = 0; mt < 2; mt++) {
                int r0 = mq * 32 + mt * 16 + (l >> 2);
                int cc = nh * 32 + (l & 3) * 2;
                #pragma unroll
                for (int nb = 0; nb < 4; nb++) {
                    *(float2*)&spill[r0 * 68 + nb * 8 + cc] =
                        make_float2(d[mt][nb][0], d[mt][nb][1]);
                    *(float2*)&spill[(r0 + 8) * 68 + nb * 8 + cc] =
                        make_float2(d[mt][nb][2], d[mt][nb][3]);
                    d[mt][nb][0] = d[mt][nb][1] = d[mt][nb][2] = d[mt][nb][3] = 0.0f;
                }
            }
        }

        const uint32_t st = sb + (c % 3) * STG;
        const uint32_t bslot = st + 8192 + gate * 8192;
        const int kkmax = (c == 17) ? 1 : 4;
        #pragma unroll
        for (int kk = 0; kk < 4; kk++) {
            if (kk >= kkmax) break;
            uint32_t b[2][4];
            #pragma unroll
            for (int nq = 0; nq < 2; nq++) {     // B (trans, slower) first
                int k = kk * 16 + (l & 15);
                int ng = nh * 4 + nq * 2 + (l >> 4);
                ldsm4t(b[nq], bslot + k * 128 + ((ng ^ (k & 7)) << 4));
            }
            uint32_t a[2][4];
            #pragma unroll
            for (int mt = 0; mt < 2; mt++) {
                int m = mq * 32 + mt * 16 + (l & 15);
                int kg = kk * 2 + (l >> 4);
                ldsm4(a[mt], st + m * 128 + ((kg ^ (m & 7)) << 4));
            }
            #pragma unroll
            for (int mt = 0; mt < 2; mt++)
                #pragma unroll
                for (int nb = 0; nb < 4; nb++)
                    mma16816(d[mt][nb], a[mt], b[nb >> 1] + (nb & 1) * 2);
        }
    }
    __syncthreads();   // all compute done; stages reusable

    // fc1 weight slice load into W1 region (overlaps epilogue below)
    if (do_fc1) {
        #pragma unroll
        for (int i = 0; i < 3; i++) {
            int v = tid + i * 384;
            if (v < 1024) {
                int s = v >> 9, r = (v >> 3) & 63, cg = v & 7;
                cp16(sb + W1_OFF + 8192 + s * 8192 + r * 128 + ((cg ^ (r & 7)) << 4),
                     g_w1h + ((size_t)s * NH + j0 + r) * 64 + cg * 8);
            }
        }
        cp_commit();
    }

    // ---- epilogue: planes r | z | i_n in sC [64][196]; h_n in spill ----
    float* sC = (float*)sm;
    #pragma unroll
    for (int mt = 0; mt < 2; mt++) {
        int r0 = mq * 32 + mt * 16 + (l >> 2);
        int cc = gate * 64 + nh * 32 + (l & 3) * 2;
        #pragma unroll
        for (int nb = 0; nb < 4; nb++) {
            *(float2*)&sC[r0 * 196 + cc + nb * 8] =
                make_float2(d[mt][nb][0], d[mt][nb][1]);
            *(float2*)&sC[(r0 + 8) * 196 + cc + nb * 8] =
                make_float2(d[mt][nb][2], d[mt][nb][3]);
        }
    }
    __syncthreads();

    #pragma unroll
    for (int i = 0; i < 11; i++) {
        int idx = i * 384 + tid;
        if (idx >= 64 * 64) break;
        int m = idx >> 6, j = idx & 63;
        int jg = j0 + j;
        float rc = sC[m * 196 + j];
        float zc = sC[m * 196 + 64 + j];
        float ic = sC[m * 196 + 128 + j];
        float hc = spill[m * 68 + j];
        float br  = __ldg(&bih[jg]) + __ldg(&bhh[jg]);
        float bz  = __ldg(&bih[NH + jg]) + __ldg(&bhh[NH + jg]);
        float bin = __ldg(&bih[2 * NH + jg]);
        float bhn = __ldg(&bhh[2 * NH + jg]);
        float r = sigf(rc + br);
        float z = sigf(zc + bz);
        float n = tanhfast(ic + bin + r * (hc + bhn));
        float hold = __half2float(hcur[(size_t)(m0 + m) * NH + jg]);
        float hnew = (1.0f - z) * n + z * hold;
        __half h16 = __float2half(hnew);
        g_h16[nxt][(size_t)(m0 + m) * NH + jg] = h16;
        if (do_fc1)   // W1 region: h tile k-major for the fc1 MMA
            *(__half*)(sm + W1_OFF + sw((uint32_t)(m * 128 + j * 2))) = h16;
    }

    if (do_fc1) {
        asm volatile("cp.async.wait_group 0;" ::: "memory");
        __syncthreads();
        // 64m x 128n(i pad) x 64k(j): 8 warps, warp tile 32x32
        if (wid < 8) {
            const int wm = wid >> 2, wn = wid & 3;
            float d2[2][4][4] = {};
            const uint32_t ab = sb + W1_OFF;
            const uint32_t bb = sb + W1_OFF + 8192 + (wn >> 1) * 8192;
            #pragma unroll
            for (int kk = 0; kk < 4; kk++) {
                uint32_t a[2][4];
                #pragma unroll
                for (int mt = 0; mt < 2; mt++) {
                    int m = wm * 32 + mt * 16 + (l & 15);
                    int kg = kk * 2 + (l >> 4);
                    ldsm4(a[mt], ab + m * 128 + ((kg ^ (m & 7)) << 4));
                }
                uint32_t b[2][4];
                #pragma unroll
                for (int nq = 0; nq < 2; nq++) {
                    int k = kk * 16 + (l & 15);
                    int ng = (wn & 1) * 4 + nq * 2 + (l >> 4);
                    ldsm4t(b[nq], bb + k * 128 + ((ng ^ (k & 7)) << 4));
                }
                #pragma unroll
                for (int mt = 0; mt < 2; mt++)
                    #pragma unroll
                    for (int nb = 0; nb < 4; nb++)
                        mma16816(d2[mt][nb], a[mt], b[nb >> 1] + (nb & 1) * 2);
            }
            // store partials (only i < 69)
            #pragma unroll
            for (int mt = 0; mt < 2; mt++) {
                int mg = m0 + wm * 32 + mt * 16 + (l >> 2);
                #pragma unroll
                for (int nb = 0; nb < 4; nb++) {
                    int n = wn * 32 + nb * 8 + (l & 3) * 2;
                    size_t base = (size_t)jt * NB * NI;
                    if (n < NI)     g_part[base + (size_t)mg * NI + n]       = d2[mt][nb][0];
                    if (n + 1 < NI) g_part[base + (size_t)mg * NI + n + 1]   = d2[mt][nb][1];
                    if (n < NI)     g_part[base + (size_t)(mg + 8) * NI + n] = d2[mt][nb][2];
                    if (n + 1 < NI) g_part[base + (size_t)(mg + 8) * NI + n + 1] = d2[mt][nb][3];
                }
            }
        }
    }
}

// out[t] = x + fc1_b + sum of 16 j-tile partials ; becomes next step's x
__global__ void k_outred(const float* __restrict__ fc1b, int t) {
    int idx = blockIdx.x * blockDim.x + threadIdx.x;
    if (idx >= NB * NI) return;
    int b = idx / NI, i = idx - b * NI;
    float s = g_x32[(size_t)b * KX + i] + fc1b[i];
    #pragma unroll
    for (int p = 0; p < 16; p++) s += g_part[(size_t)p * NB * NI + idx];
    g_outb[(size_t)t * NB * NI + idx] = s;
    g_x32[(size_t)b * KX + i] = s;
    g_xdec[(size_t)b * KX + i] = __float2half(s);
}

__global__ void k_final(const float* __restrict__ fc2w, const float* __restrict__ fc2b,
                        float* __restrict__ y) {
    int b = blockIdx.x;
    float s = 0.0f;
    for (int f = threadIdx.x; f < NT * NI; f += 256) {
        int t = f / NI, i = f - t * NI;
        s += g_outb[(size_t)t * NB * NI + (size_t)b * NI + i] * fc2w[f];
    }
    __shared__ float red[256];
    red[threadIdx.x] = s;
    __syncthreads();
    for (int off = 128; off > 0; off >>= 1) {
        if (threadIdx.x < off) red[threadIdx.x] += red[threadIdx.x + off];
        __syncthreads();
    }
    if (threadIdx.x == 0)
        y[b] = 1.0f / (1.0f + expf(-(red[0] + fc2b[0])));
}

// ---------------- launch ----------------
extern "C" void kernel_launch(void* const* d_in, const int* in_sizes, int n_in,
                              void* d_out, int out_size) {
    const float* enc  = (const float*)d_in[0];
    const float* dec  = (const float*)d_in[1];
    const float* w_ih = (const float*)d_in[2];
    const float* w_hh = (const float*)d_in[3];
    const float* b_ih = (const float*)d_in[4];
    const float* b_hh = (const float*)d_in[5];
    const float* fc1w = (const float*)d_in[6];
    const float* fc1b = (const float*)d_in[7];
    const float* fc2w = (const float*)d_in[8];
    const float* fc2b = (const float*)d_in[9];
    float* y = (float*)d_out;

    cudaFuncSetAttribute(k_gru, cudaFuncAttributeMaxDynamicSharedMemorySize, SMEM_BYTES);

    k_prep<<<(int)(((size_t)4 * KA * NH + 255) / 256), 256>>>(w_ih, w_hh);
    k_prepw<<<(2 * NH * 64 + 255) / 256, 256>>>(fc1w);
    k_setxall<<<(int)(((size_t)NT * NB * KX + 255) / 256), 256>>>(enc, dec);
    k_init<<<(NB * NH + 255) / 256, 256>>>();

    int cur = 0;
    for (int s = 0; s < NSTEP; ++s) {
        int xsel;
        if (s < NT)       xsel = s;    // encode frames 0..73
        else if (s == NT) xsel = 0;    // first decode step uses frame 0
        else              xsel = -1;   // autoregressive: g_xdec
        int do_fc1 = (s >= NT) ? 1 : 0;
        int c0 = (s == 0) ? 16 : 0;    // step 0: h == 0, skip h chunks
        k_gru<<<dim3(16, 16), 384, SMEM_BYTES>>>(cur, b_ih, b_hh, do_fc1, xsel, c0);
        if (s >= NT)
            k_outred<<<(NB * NI + 255) / 256, 256>>>(fc1b, s - NT);
        cur ^= 1;
    }
    k_final<<<NB, 256>>>(fc2w, fc2b, y);
}

// round 17
// speedup vs baseline: 1.3052x; 1.0303x over previous
#include <cuda_runtime.h>
#include <cuda_fp16.h>
#include <cstdint>
#include <math.h>

// ---------------- problem constants ----------------
constexpr int NB   = 1024;
constexpr int NH   = 1024;
constexpr int NI   = 69;
constexpr int NSRC = 50;
constexpr int NDEC = 24;
constexpr int NT   = 74;
constexpr int KX   = 128;
constexpr int KA   = NH + KX;     // 1152
constexpr int NSTEP = 2 * NT;     // 148

constexpr int STG  = 32768;               // A 8KB + B 3x8KB per stage
constexpr int SPILL_OFF = 3 * STG;        // 98304: h_n spill [64][68] fp32
constexpr int SMEM_BYTES = SPILL_OFF + 64 * 68 * 4;   // 115712 (2 CTAs/SM)
constexpr int W1_OFF = 2 * STG;           // fc1: h tile @ stage2, w1 @ stage2+8KB

// ---------------- device scratch ----------------
__device__ __align__(16) __half g_h16[2][NB * NH];   // fp16 hidden state (sole copy)
__device__ __align__(16) __half g_xall[NT * NB * KX];// all encode frames fp16 (padded)
__device__ __align__(16) __half g_xdec[NB * KX];     // decode-time x fp16 (padded)
__device__ __align__(16) __half g_wB[4 * KA * NH];   // [g][k][j] fp16
__device__ __align__(16) __half g_w1h[2 * NH * 64];  // fc1 w [slot][j][i-in-slot] fp16
__device__ __align__(16) float  g_x32[NB * KX];
__device__ __align__(16) float  g_outb[NT * NB * NI];
__device__ __align__(16) float  g_part[16 * NB * NI];

// ---------------- asm helpers (base PTX only) ----------------
__device__ __forceinline__ uint32_t smem_u32(const void* p) {
    uint32_t a;
    asm("{ .reg .u64 t; cvta.to.shared.u64 t, %1; cvt.u32.u64 %0, t; }" : "=r"(a) : "l"(p));
    return a;
}
__device__ __forceinline__ void cp16(uint32_t dst, const void* src) {
    asm volatile("cp.async.cg.shared.global [%0], [%1], 16;" :: "r"(dst), "l"(src));
}
__device__ __forceinline__ void cp_commit() {
    asm volatile("cp.async.commit_group;" ::: "memory");
}
__device__ __forceinline__ void ldsm4(uint32_t* r, uint32_t addr) {
    asm volatile("ldmatrix.sync.aligned.m8n8.x4.shared.b16 {%0,%1,%2,%3}, [%4];"
        : "=r"(r[0]), "=r"(r[1]), "=r"(r[2]), "=r"(r[3]) : "r"(addr));
}
__device__ __forceinline__ void ldsm4t(uint32_t* r, uint32_t addr) {
    asm volatile("ldmatrix.sync.aligned.m8n8.x4.trans.shared.b16 {%0,%1,%2,%3}, [%4];"
        : "=r"(r[0]), "=r"(r[1]), "=r"(r[2]), "=r"(r[3]) : "r"(addr));
}
__device__ __forceinline__ void mma16816(float* d, const uint32_t* a, const uint32_t* b) {
    asm volatile("mma.sync.aligned.m16n8k16.row.col.f32.f16.f16.f32 "
        "{%0,%1,%2,%3}, {%4,%5,%6,%7}, {%8,%9}, {%0,%1,%2,%3};"
        : "+f"(d[0]), "+f"(d[1]), "+f"(d[2]), "+f"(d[3])
        : "r"(a[0]), "r"(a[1]), "r"(a[2]), "r"(a[3]), "r"(b[0]), "r"(b[1]));
}
__device__ __forceinline__ uint32_t sw(uint32_t bo) { return bo ^ ((bo >> 3) & 0x70); }

// fast sigmoid: EX2 + RCP + 1 Newton step (rel err ~1e-7)
__device__ __forceinline__ float sigf(float x) {
    float t = fminf(fmaxf(x, -30.f), 30.f);
    float e;
    asm("ex2.approx.f32 %0, %1;" : "=f"(e) : "f"(-1.4426950408889634f * t));
    float den = 1.0f + e;
    float r;
    asm("rcp.approx.f32 %0, %1;" : "=f"(r) : "f"(den));
    return r * (2.0f - den * r);
}
__device__ __forceinline__ float tanhfast(float x) { return 1.0f - 2.0f * sigf(-2.0f * x); }

// ---------------- prep: per-gate K-major fp16 weights ----------------
__global__ void k_prep(const float* __restrict__ w_ih, const float* __restrict__ w_hh) {
    size_t idx = (size_t)blockIdx.x * blockDim.x + threadIdx.x;
    if (idx >= (size_t)4 * KA * NH) return;
    int j = (int)(idx % NH);
    int t = (int)(idx / NH);
    int k = t % KA;
    int g = t / KA;
    float v = 0.0f;
    if (g == 0) {
        if (k < NH) v = w_hh[(size_t)j * NH + k];
        else if (k - NH < NI) v = w_ih[(size_t)j * NI + (k - NH)];
    } else if (g == 1) {
        if (k < NH) v = w_hh[(size_t)(NH + j) * NH + k];
        else if (k - NH < NI) v = w_ih[(size_t)(NH + j) * NI + (k - NH)];
    } else if (g == 2) {
        if (k >= NH && k - NH < NI) v = w_ih[(size_t)(2 * NH + j) * NI + (k - NH)];
    } else {
        if (k < NH) v = w_hh[(size_t)(2 * NH + j) * NH + k];
    }
    g_wB[idx] = __float2half(v);
}

// fc1 weights, per 64-wide i-slot: g_w1h[s][j][n], i = s*64+n
__global__ void k_prepw(const float* __restrict__ fc1w) {
    int idx = blockIdx.x * blockDim.x + threadIdx.x;
    if (idx >= 2 * NH * 64) return;
    int n = idx & 63;
    int j = (idx >> 6) & (NH - 1);
    int s = idx >> 16;
    int i = s * 64 + n;
    float v = (i < NI) ? fc1w[(size_t)i * NH + j] : 0.0f;
    g_w1h[idx] = __float2half(v);
}

// one-shot: convert ALL encode frames to fp16 padded; frame 0 also -> g_x32
__global__ void k_setxall(const float* __restrict__ enc, const float* __restrict__ dec) {
    size_t idx = (size_t)blockIdx.x * blockDim.x + threadIdx.x;
    if (idx >= (size_t)NT * NB * KX) return;
    int c = (int)(idx & (KX - 1));
    size_t r = idx >> 7;
    int b = (int)(r & (NB - 1));
    int t = (int)(r >> 10);
    float v = 0.0f;
    if (c < NI) {
        if (t < NSRC) v = enc[((size_t)b * NSRC + t) * NI + c];
        else          v = dec[((size_t)b * NDEC + (t - NSRC)) * NI + c];
    }
    g_xall[idx] = __float2half(v);
    if (t == 0) g_x32[(size_t)b * KX + c] = v;
}

__global__ void k_init() {
    int idx = blockIdx.x * blockDim.x + threadIdx.x;
    if (idx < NB * NH) g_h16[0][idx] = __float2half(0.0f);
    if (idx < NB * KX) g_xdec[idx] = __float2half(0.0f);
}

// ---------------- fused GRU step ----------------
// grid (16 j-tiles, 16 m-tiles), 384 threads = 12 warps, 2 CTAs/SM.
// warp: gate = wid>>2 (0=r,1=z,2=n-slot); mq = (wid>>1)&1; nh = wid&1.
// CTA tile 64m x 64j, warp tile 32m x 32n. 3-stage ring, one barrier/chunk.
// Main loop c = c0..16 (full chunks, kk fully unrolled); chunk 17 PEELED
// (only 16 k-rows carry data: x cols 64..68, rest zero).
__global__ void __launch_bounds__(384, 2)
k_gru(int cur, const float* __restrict__ bih, const float* __restrict__ bhh,
      int do_fc1, int xsel, int c0) {
    extern __shared__ char sm[];
    const uint32_t sb = smem_u32(sm);
    const int tid = threadIdx.x;
    const int wid = tid >> 5, l = tid & 31;
    const int gate = wid >> 2;
    const int mq = (wid >> 1) & 1, nh = wid & 1;
    const int m0 = blockIdx.y * 64;
    const int j0 = blockIdx.x * 64;
    const int jt = blockIdx.x;
    const int nxt = cur ^ 1;

    const __half* hcur = g_h16[cur];
    const __half* xb = (xsel >= 0) ? (g_xall + (size_t)xsel * NB * KX) : g_xdec;

    float d[2][4][4] = {};   // [mt][nb][frag]

    auto load_chunk = [&](int c) {
        const uint32_t st = sb + (c % 3) * STG;
        if (c == 17) {
            // short chunk: A 128 granules (64m x 2kg), B 384 (3 slots x 16k x 8cg)
            #pragma unroll
            for (int i = 0; i < 2; i++) {
                int v = tid + i * 384;
                if (v < 128) {
                    int m = v >> 1, kg = v & 1;
                    cp16(st + m * 128 + ((kg ^ (m & 7)) << 4),
                         xb + (size_t)(m0 + m) * KX + 64 + kg * 8);
                } else if (v < 512) {
                    int u = v - 128;
                    int tb = u >> 7;                 // 0..2 gate slot
                    int r = (u >> 3) & 15, cg = u & 7;
                    int g = (tb < 2) ? tb : 2;
                    cp16(st + 8192 + tb * 8192 + r * 128 + ((cg ^ (r & 7)) << 4),
                         g_wB + ((size_t)g * KA + 17 * 64 + r) * NH + j0 + cg * 8);
                }
            }
        } else {
            // full chunk: 2048 granules: A 512 (64m x 8kg), B 1536 (3 x 64k x 8cg)
            #pragma unroll
            for (int i = 0; i < 6; i++) {
                int v = tid + i * 384;
                if (v < 512) {
                    int m = v >> 3, kg = v & 7;
                    const __half* src = (c < 16)
                        ? hcur + (size_t)(m0 + m) * NH + c * 64 + kg * 8
                        : xb   + (size_t)(m0 + m) * KX + kg * 8;   // c == 16
                    cp16(st + m * 128 + ((kg ^ (m & 7)) << 4), src);
                } else if (v < 2048) {
                    int u = v - 512;
                    int tb = u >> 9;                 // 0..2 gate slot
                    int r = (u >> 3) & 63, cg = u & 7;
                    int g = (tb < 2) ? tb : ((c < 16) ? 3 : 2);
                    cp16(st + 8192 + tb * 8192 + r * 128 + ((cg ^ (r & 7)) << 4),
                         g_wB + ((size_t)g * KA + c * 64 + r) * NH + j0 + cg * 8);
                }
            }
        }
        cp_commit();
    };

    float* spill = (float*)(sm + SPILL_OFF);   // [64][68]

    load_chunk(c0);
    load_chunk(c0 + 1);

    // ---- main loop: FULL chunks c0..16, branch-free unrolled compute ----
    for (int c = c0; c < 17; c++) {
        asm volatile("cp.async.wait_group 1;" ::: "memory");
        __syncthreads();   // the ONLY barrier per chunk

        if (c + 2 <= 17) load_chunk(c + 2);

        // n-slot boundary: stash h_n accum, restart for i_n
        // (at c0==16 this stores zeros == correct h_n for h==0)
        if (c == 16 && gate == 2) {
            #pragma unroll
            for (int mt = 0; mt < 2; mt++) {
                int r0 = mq * 32 + mt * 16 + (l >> 2);
                int cc = nh * 32 + (l & 3) * 2;
                #pragma unroll
                for (int nb = 0; nb < 4; nb++) {
                    *(float2*)&spill[r0 * 68 + nb * 8 + cc] =
                        make_float2(d[mt][nb][0], d[mt][nb][1]);
                    *(float2*)&spill[(r0 + 8) * 68 + nb * 8 + cc] =
                        make_float2(d[mt][nb][2], d[mt][nb][3]);
                    d[mt][nb][0] = d[mt][nb][1] = d[mt][nb][2] = d[mt][nb][3] = 0.0f;
                }
            }
        }

        const uint32_t st = sb + (c % 3) * STG;
        const uint32_t bslot = st + 8192 + gate * 8192;
        #pragma unroll
        for (int kk = 0; kk < 4; kk++) {
            uint32_t b[2][4];
            #pragma unroll
            for (int nq = 0; nq < 2; nq++) {     // B (trans, slower) first
                int k = kk * 16 + (l & 15);
                int ng = nh * 4 + nq * 2 + (l >> 4);
                ldsm4t(b[nq], bslot + k * 128 + ((ng ^ (k & 7)) << 4));
            }
            uint32_t a[2][4];
            #pragma unroll
            for (int mt = 0; mt < 2; mt++) {
                int m = mq * 32 + mt * 16 + (l & 15);
                int kg = kk * 2 + (l >> 4);
                ldsm4(a[mt], st + m * 128 + ((kg ^ (m & 7)) << 4));
            }
            #pragma unroll
            for (int mt = 0; mt < 2; mt++)
                #pragma unroll
                for (int nb = 0; nb < 4; nb++)
                    mma16816(d[mt][nb], a[mt], b[nb >> 1] + (nb & 1) * 2);
        }
    }

    // ---- peeled SHORT chunk 17: single kk step ----
    {
        asm volatile("cp.async.wait_group 0;" ::: "memory");
        __syncthreads();
        const uint32_t st = sb + (17 % 3) * STG;
        const uint32_t bslot = st + 8192 + gate * 8192;
        uint32_t b[2][4];
        #pragma unroll
        for (int nq = 0; nq < 2; nq++) {
            int k = l & 15;
            int ng = nh * 4 + nq * 2 + (l >> 4);
            ldsm4t(b[nq], bslot + k * 128 + ((ng ^ (k & 7)) << 4));
        }
        uint32_t a[2][4];
        #pragma unroll
        for (int mt = 0; mt < 2; mt++) {
            int m = mq * 32 + mt * 16 + (l & 15);
            int kg = l >> 4;
            ldsm4(a[mt], st + m * 128 + ((kg ^ (m & 7)) << 4));
        }
        #pragma unroll
        for (int mt = 0; mt < 2; mt++)
            #pragma unroll
            for (int nb = 0; nb < 4; nb++)
                mma16816(d[mt][nb], a[mt], b[nb >> 1] + (nb & 1) * 2);
    }
    __syncthreads();   // all compute done; stages reusable

    // fc1 weight slice load into W1 region (overlaps epilogue below)
    if (do_fc1) {
        #pragma unroll
        for (int i = 0; i < 3; i++) {
            int v = tid + i * 384;
            if (v < 1024) {
                int s = v >> 9, r = (v >> 3) & 63, cg = v & 7;
                cp16(sb + W1_OFF + 8192 + s * 8192 + r * 128 + ((cg ^ (r & 7)) << 4),
                     g_w1h + ((size_t)s * NH + j0 + r) * 64 + cg * 8);
            }
        }
        cp_commit();
    }

    // ---- epilogue: planes r | z | i_n in sC [64][196]; h_n in spill ----
    float* sC = (float*)sm;
    #pragma unroll
    for (int mt = 0; mt < 2; mt++) {
        int r0 = mq * 32 + mt * 16 + (l >> 2);
        int cc = gate * 64 + nh * 32 + (l & 3) * 2;
        #pragma unroll
        for (int nb = 0; nb < 4; nb++) {
            *(float2*)&sC[r0 * 196 + cc + nb * 8] =
                make_float2(d[mt][nb][0], d[mt][nb][1]);
            *(float2*)&sC[(r0 + 8) * 196 + cc + nb * 8] =
                make_float2(d[mt][nb][2], d[mt][nb][3]);
        }
    }
    __syncthreads();

    #pragma unroll
    for (int i = 0; i < 11; i++) {
        int idx = i * 384 + tid;
        if (idx >= 64 * 64) break;
        int m = idx >> 6, j = idx & 63;
        int jg = j0 + j;
        float rc = sC[m * 196 + j];
        float zc = sC[m * 196 + 64 + j];
        float ic = sC[m * 196 + 128 + j];
        float hc = spill[m * 68 + j];
        float br  = __ldg(&bih[jg]) + __ldg(&bhh[jg]);
        float bz  = __ldg(&bih[NH + jg]) + __ldg(&bhh[NH + jg]);
        float bin = __ldg(&bih[2 * NH + jg]);
        float bhn = __ldg(&bhh[2 * NH + jg]);
        float r = sigf(rc + br);
        float z = sigf(zc + bz);
        float n = tanhfast(ic + bin + r * (hc + bhn));
        float hold = __half2float(hcur[(size_t)(m0 + m) * NH + jg]);
        float hnew = (1.0f - z) * n + z * hold;
        __half h16 = __float2half(hnew);
        g_h16[nxt][(size_t)(m0 + m) * NH + jg] = h16;
        if (do_fc1)   // W1 region: h tile k-major for the fc1 MMA
            *(__half*)(sm + W1_OFF + sw((uint32_t)(m * 128 + j * 2))) = h16;
    }

    if (do_fc1) {
        asm volatile("cp.async.wait_group 0;" ::: "memory");
        __syncthreads();
        // 64m x 128n(i pad) x 64k(j): 8 warps, warp tile 32x32
        if (wid < 8) {
            const int wm = wid >> 2, wn = wid & 3;
            float d2[2][4][4] = {};
            const uint32_t ab = sb + W1_OFF;
            const uint32_t bb = sb + W1_OFF + 8192 + (wn >> 1) * 8192;
            #pragma unroll
            for (int kk = 0; kk < 4; kk++) {
                uint32_t a[2][4];
                #pragma unroll
                for (int mt = 0; mt < 2; mt++) {
                    int m = wm * 32 + mt * 16 + (l & 15);
                    int kg = kk * 2 + (l >> 4);
                    ldsm4(a[mt], ab + m * 128 + ((kg ^ (m & 7)) << 4));
                }
                uint32_t b[2][4];
                #pragma unroll
                for (int nq = 0; nq < 2; nq++) {
                    int k = kk * 16 + (l & 15);
                    int ng = (wn & 1) * 4 + nq * 2 + (l >> 4);
                    ldsm4t(b[nq], bb + k * 128 + ((ng ^ (k & 7)) << 4));
                }
                #pragma unroll
                for (int mt = 0; mt < 2; mt++)
                    #pragma unroll
                    for (int nb = 0; nb < 4; nb++)
                        mma16816(d2[mt][nb], a[mt], b[nb >> 1] + (nb & 1) * 2);
            }
            // store partials (only i < 69)
            #pragma unroll
            for (int mt = 0; mt < 2; mt++) {
                int mg = m0 + wm * 32 + mt * 16 + (l >> 2);
                #pragma unroll
                for (int nb = 0; nb < 4; nb++) {
                    int n = wn * 32 + nb * 8 + (l & 3) * 2;
                    size_t base = (size_t)jt * NB * NI;
                    if (n < NI)     g_part[base + (size_t)mg * NI + n]       = d2[mt][nb][0];
                    if (n + 1 < NI) g_part[base + (size_t)mg * NI + n + 1]   = d2[mt][nb][1];
                    if (n < NI)     g_part[base + (size_t)(mg + 8) * NI + n] = d2[mt][nb][2];
                    if (n + 1 < NI) g_part[base + (size_t)(mg + 8) * NI + n + 1] = d2[mt][nb][3];
                }
            }
        }
    }
}

// out[t] = x + fc1_b + sum of 16 j-tile partials ; becomes next step's x
__global__ void k_outred(const float* __restrict__ fc1b, int t) {
    int idx = blockIdx.x * blockDim.x + threadIdx.x;
    if (idx >= NB * NI) return;
    int b = idx / NI, i = idx - b * NI;
    float s = g_x32[(size_t)b * KX + i] + fc1b[i];
    #pragma unroll
    for (int p = 0; p < 16; p++) s += g_part[(size_t)p * NB * NI + idx];
    g_outb[(size_t)t * NB * NI + idx] = s;
    g_x32[(size_t)b * KX + i] = s;
    g_xdec[(size_t)b * KX + i] = __float2half(s);
}

__global__ void k_final(const float* __restrict__ fc2w, const float* __restrict__ fc2b,
                        float* __restrict__ y) {
    int b = blockIdx.x;
    float s = 0.0f;
    for (int f = threadIdx.x; f < NT * NI; f += 256) {
        int t = f / NI, i = f - t * NI;
        s += g_outb[(size_t)t * NB * NI + (size_t)b * NI + i] * fc2w[f];
    }
    __shared__ float red[256];
    red[threadIdx.x] = s;
    __syncthreads();
    for (int off = 128; off > 0; off >>= 1) {
        if (threadIdx.x < off) red[threadIdx.x] += red[threadIdx.x + off];
        __syncthreads();
    }
    if (threadIdx.x == 0)
        y[b] = 1.0f / (1.0f + expf(-(red[0] + fc2b[0])));
}

// ---------------- launch ----------------
extern "C" void kernel_launch(void* const* d_in, const int* in_sizes, int n_in,
                              void* d_out, int out_size) {
    const float* enc  = (const float*)d_in[0];
    const float* dec  = (const float*)d_in[1];
    const float* w_ih = (const float*)d_in[2];
    const float* w_hh = (const float*)d_in[3];
    const float* b_ih = (const float*)d_in[4];
    const float* b_hh = (const float*)d_in[5];
    const float* fc1w = (const float*)d_in[6];
    const float* fc1b = (const float*)d_in[7];
    const float* fc2w = (const float*)d_in[8];
    const float* fc2b = (const float*)d_in[9];
    float* y = (float*)d_out;

    cudaFuncSetAttribute(k_gru, cudaFuncAttributeMaxDynamicSharedMemorySize, SMEM_BYTES);

    k_prep<<<(int)(((size_t)4 * KA * NH + 255) / 256), 256>>>(w_ih, w_hh);
    k_prepw<<<(2 * NH * 64 + 255) / 256, 256>>>(fc1w);
    k_setxall<<<(int)(((size_t)NT * NB * KX + 255) / 256), 256>>>(enc, dec);
    k_init<<<(NB * NH + 255) / 256, 256>>>();

    int cur = 0;
    for (int s = 0; s < NSTEP; ++s) {
        int xsel;
        if (s < NT)       xsel = s;    // encode frames 0..73
        else if (s == NT) xsel = 0;    // first decode step uses frame 0
        else              xsel = -1;   // autoregressive: g_xdec
        int do_fc1 = (s >= NT) ? 1 : 0;
        int c0 = (s == 0) ? 16 : 0;    // step 0: h == 0, skip h chunks
        k_gru<<<dim3(16, 16), 384, SMEM_BYTES>>>(cur, b_ih, b_hh, do_fc1, xsel, c0);
        if (s >= NT)
            k_outred<<<(NB * NI + 255) / 256, 256>>>(fc1b, s - NT);
        cur ^= 1;
    }
    k_final<<<NB, 256>>>(fc2w, fc2b, y);
}